// round 5
// baseline (speedup 1.0000x reference)
#include <cuda_runtime.h>
#include <math.h>
#include <stdint.h>

#define MAXB 8192

__device__ float g_conv1[(size_t)MAXB * 64 * 400];   // [B,64,20,20]
__device__ float g_pool1[(size_t)MAXB * 64 * 100];   // [B,64,10,10]
__device__ float g_conv2[(size_t)MAXB * 128 * 100];  // [B,128,10,10]
__device__ float g_pool2[(size_t)MAXB * 128 * 25];   // [B,128,5,5]
__device__ float g_conv3[(size_t)MAXB * 256 * 25];   // [B,256,5,5]
__device__ float g_feat [(size_t)25 * MAXB * 256];   // [25,B,256]
__device__ float g_preds[(size_t)25 * MAXB * 10];    // [25,B,10]
__device__ float g_scale[704];
__device__ float g_bias[704];

// ---------------------------------------------------------------------------
// Packed f32x2 helpers (Blackwell FFMA2 — 2 fp32 FMAs per fma-pipe slot)
// ---------------------------------------------------------------------------
typedef unsigned long long ull;

__device__ __forceinline__ ull pack2(float lo, float hi) {
    ull r;
    asm("mov.b64 %0, {%1, %2};" : "=l"(r) : "f"(lo), "f"(hi));
    return r;
}
__device__ __forceinline__ void fma2(ull& d, ull a, ull b) {
    asm("fma.rn.f32x2 %0, %1, %2, %3;" : "=l"(d) : "l"(a), "l"(b), "l"(d));
}
__device__ __forceinline__ void unpack2(ull v, float& lo, float& hi) {
    asm("mov.b64 {%0, %1}, %2;" : "=f"(lo), "=f"(hi) : "l"(v));
}

// ---------------------------------------------------------------------------
// BN fold
// ---------------------------------------------------------------------------
__global__ void bn_prep(const float* __restrict__ b, const float* __restrict__ g,
                        const float* __restrict__ be, const float* __restrict__ m,
                        const float* __restrict__ v, int C, int off)
{
    int c = blockIdx.x * blockDim.x + threadIdx.x;
    if (c < C) {
        float sc = g[c] / sqrtf(v[c] + 1e-5f);
        g_scale[off + c] = sc;
        g_bias[off + c]  = (b[c] - m[c]) * sc + be[c];
    }
}

// ---------------------------------------------------------------------------
// 3x3 conv (pad 1) + folded BN + ReLU, FFMA2 inner loop.
// Block = (5x5 tile, image). Thread = out-channel.
// Output row of 5 pixels packed as {0,1},{2,3},{4}.
// ---------------------------------------------------------------------------
template<int IC, int OC, int ICCHUNK, int HW, int NTHREADS, bool FEATOUT>
__launch_bounds__(NTHREADS, 2)
__global__ void conv_bn_relu_kernel(const float* __restrict__ in,
                                    const float* __restrict__ wt,
                                    const float* __restrict__ ks,
                                    const float* __restrict__ kb,
                                    float* __restrict__ out, int B)
{
    constexpr int TILES = HW / 5;
    constexpr int CH9 = ICCHUNK * 9;
    constexpr int WSTRIDE = (CH9 % 2 == 0) ? (CH9 + 1) : CH9;

    extern __shared__ float dyn[];
    float* in_s = dyn;                      // ICCHUNK*49
    float* w_s  = dyn + ICCHUNK * 49;       // OC*WSTRIDE

    const int tile = blockIdx.x;
    const int b    = blockIdx.y;
    const int ty0  = (tile / TILES) * 5;
    const int tx0  = (tile % TILES) * 5;
    const int oc   = threadIdx.x;           // NTHREADS == OC

    ull   accp[5][2];
    float acc4[5];
    #pragma unroll
    for (int r = 0; r < 5; r++) {
        accp[r][0] = 0ull; accp[r][1] = 0ull; acc4[r] = 0.f;
    }

    for (int ic0 = 0; ic0 < IC; ic0 += ICCHUNK) {
        __syncthreads();
        for (int idx = threadIdx.x; idx < ICCHUNK * 49; idx += NTHREADS) {
            int i = idx / 49, r = idx % 49;
            int y = ty0 - 1 + r / 7;
            int x = tx0 - 1 + r % 7;
            float v = 0.f;
            if (y >= 0 && y < HW && x >= 0 && x < HW)
                v = in[(((size_t)b * IC + ic0 + i) * HW + y) * HW + x];
            in_s[idx] = v;
        }
        for (int idx = threadIdx.x; idx < OC * CH9; idx += NTHREADS) {
            int o = idx / CH9, r = idx % CH9;
            w_s[o * WSTRIDE + r] = wt[((size_t)o * IC + ic0) * 9 + r];
        }
        __syncthreads();

        #pragma unroll 1
        for (int i = 0; i < ICCHUNK; i++) {
            float ws[9];
            ull   wp2[9];
            const float* wq = &w_s[oc * WSTRIDE + i * 9];
            #pragma unroll
            for (int k = 0; k < 9; k++) {
                ws[k]  = wq[k];
                wp2[k] = pack2(ws[k], ws[k]);
            }
            #pragma unroll
            for (int r = 0; r < 7; r++) {
                float iv[7];
                #pragma unroll
                for (int c = 0; c < 7; c++) iv[c] = in_s[i * 49 + r * 7 + c];
                ull pr[5];
                #pragma unroll
                for (int s = 0; s < 5; s++) pr[s] = pack2(iv[s], iv[s + 1]);
                #pragma unroll
                for (int ky = 0; ky < 3; ky++) {
                    const int py = r - ky;
                    if (py >= 0 && py < 5) {
                        #pragma unroll
                        for (int kx = 0; kx < 3; kx++) {
                            fma2(accp[py][0], wp2[ky * 3 + kx], pr[kx]);
                            fma2(accp[py][1], wp2[ky * 3 + kx], pr[kx + 2]);
                            acc4[py] = fmaf(ws[ky * 3 + kx], iv[kx + 4], acc4[py]);
                        }
                    }
                }
            }
        }
    }

    float s  = ks[oc];
    float bs = kb[oc];
    #pragma unroll
    for (int py = 0; py < 5; py++) {
        float v0, v1, v2, v3;
        unpack2(accp[py][0], v0, v1);
        unpack2(accp[py][1], v2, v3);
        float row[5] = { v0, v1, v2, v3, acc4[py] };
        #pragma unroll
        for (int px = 0; px < 5; px++) {
            float y = fmaxf(fmaf(row[px], s, bs), 0.f);
            if (FEATOUT) {
                int node = py * 5 + px;     // HW==5, single tile
                out[((size_t)node * B + b) * OC + oc] = y;
            } else {
                out[(((size_t)b * OC + oc) * HW + ty0 + py) * HW + tx0 + px] = y;
            }
        }
    }
}

// ---------------------------------------------------------------------------
// MaxPool2d(3, s=2, p=1)
// ---------------------------------------------------------------------------
__global__ void maxpool_kernel(const float* __restrict__ in, float* __restrict__ out,
                               int B, int C, int H)
{
    int OH = H / 2;
    size_t total = (size_t)B * C * OH * OH;
    size_t idx = (size_t)blockIdx.x * blockDim.x + threadIdx.x;
    if (idx >= total) return;
    int ox = idx % OH;
    int oy = (idx / OH) % OH;
    size_t bc = idx / ((size_t)OH * OH);
    const float* p = in + bc * H * H;
    float m = -3.4e38f;
    #pragma unroll
    for (int dy = -1; dy <= 1; dy++) {
        int iy = 2 * oy + dy;
        if (iy < 0 || iy >= H) continue;
        #pragma unroll
        for (int dx = -1; dx <= 1; dx++) {
            int ix = 2 * ox + dx;
            if (ix < 0 || ix >= H) continue;
            m = fmaxf(m, p[iy * H + ix]);
        }
    }
    out[idx] = m;
}

// ---------------------------------------------------------------------------
// Neighbor table (exact reference ordering, w=h=5)
// ---------------------------------------------------------------------------
__device__ __forceinline__ int nei_of(int i, int j)
{
    int n[8]; int cnt = 0;
    if (i - 5 >= 0)                          n[cnt++] = i - 5;
    if (i % 5 != 0)                          n[cnt++] = i - 1;
    if ((i + 1) % 5 != 0)                    n[cnt++] = i + 1;
    if (i + 5 < 25)                          n[cnt++] = i + 5;
    if (i - 6 >= 0 && i % 5 != 0)            n[cnt++] = i - 6;
    if (i - 4 >= 0 && (i + 1) % 5 != 0)      n[cnt++] = i - 4;
    if (i + 4 < 25 && i % 5 != 0)            n[cnt++] = i + 4;
    if (i + 6 < 25 && (i + 1) % 5 != 0)      n[cnt++] = i + 6;
    while (cnt < 8) n[cnt++] = -1;
    return n[j];
}

// ---------------------------------------------------------------------------
// Fused per-node MLP with FFMA2 micro-tiles (4 batch x 2 hidden-pairs)
// ---------------------------------------------------------------------------
template<int KDIM, bool STAGE2>
__launch_bounds__(256)
__global__ void mlp_kernel(const float* __restrict__ feat,   // [25][B][256]
                           const float* __restrict__ preds,  // [25][B][10]
                           const float* __restrict__ Wa,     // [25][336][600]
                           const float* __restrict__ ba,     // [25][600]
                           const float* __restrict__ Wb,     // [25][600][10]
                           const float* __restrict__ bb,     // [25][10]
                           float* __restrict__ outp,         // [25][B][10]
                           int B)
{
    __shared__ __align__(16) float Xs[8][64];
    __shared__ __align__(16) float Was[8][64];
    __shared__ float Hcs[64][65];
    __shared__ float Wbs[64][10];
    __shared__ float lg[64][12];
    __shared__ int s_nei[8];

    const int n   = blockIdx.y;
    const int b0  = blockIdx.x * 64;
    const int tid = threadIdx.x;
    const int bgrp = tid & 15;
    const int hgrp = tid >> 4;

    if (tid < 8) s_nei[tid] = nei_of(n, tid);
    for (int idx = tid; idx < 640; idx += 256)
        lg[idx / 10][idx % 10] = bb[n * 10 + idx % 10];

    const float* Wan   = Wa + (size_t)n * 336 * 600 + (size_t)(STAGE2 ? 0 : 80) * 600;
    const float* ban   = ba + n * 600;
    const float* Wbn   = Wb + (size_t)n * 600 * 10;
    const float* featn = feat + (size_t)n * B * 256;

    for (int hc = 0; hc < 640; hc += 64) {
        ull accp[4][2];
        #pragma unroll
        for (int jp = 0; jp < 2; jp++) {
            int h0 = hc + hgrp * 4 + jp * 2;
            float bv0 = (h0     < 600) ? ban[h0]     : 0.f;
            float bv1 = (h0 + 1 < 600) ? ban[h0 + 1] : 0.f;
            ull bvp = pack2(bv0, bv1);
            #pragma unroll
            for (int i = 0; i < 4; i++) accp[i][jp] = bvp;
        }

        for (int k0 = 0; k0 < KDIM; k0 += 8) {
            __syncthreads();
            #pragma unroll
            for (int t = 0; t < 2; t++) {
                int e = tid * 2 + t;
                int bi = e >> 3, kj = e & 7;
                int k = k0 + kj;
                float v;
                if (STAGE2 && k < 80) {
                    int jn = k / 10, c = k - jn * 10;
                    int ne = s_nei[jn];
                    v = (ne >= 0) ? preds[((size_t)ne * B + b0 + bi) * 10 + c] : 0.f;
                } else {
                    int ch = STAGE2 ? (k - 80) : k;
                    v = featn[((size_t)(b0 + bi)) * 256 + ch];
                }
                Xs[kj][bi] = v;
            }
            #pragma unroll
            for (int t = 0; t < 2; t++) {
                int e = tid * 2 + t;
                int kj = e >> 6, hi = e & 63;
                int h = hc + hi;
                Was[kj][hi] = (h < 600) ? Wan[(size_t)(k0 + kj) * 600 + h] : 0.f;
            }
            __syncthreads();

            #pragma unroll
            for (int kj = 0; kj < 8; kj++) {
                float4 xv = *reinterpret_cast<const float4*>(&Xs[kj][bgrp * 4]);
                float4 wv = *reinterpret_cast<const float4*>(&Was[kj][hgrp * 4]);
                ull wh2[2] = { pack2(wv.x, wv.y), pack2(wv.z, wv.w) };
                ull xb2[4] = { pack2(xv.x, xv.x), pack2(xv.y, xv.y),
                               pack2(xv.z, xv.z), pack2(xv.w, xv.w) };
                #pragma unroll
                for (int i = 0; i < 4; i++) {
                    fma2(accp[i][0], xb2[i], wh2[0]);
                    fma2(accp[i][1], xb2[i], wh2[1]);
                }
            }
        }

        #pragma unroll
        for (int i = 0; i < 4; i++) {
            #pragma unroll
            for (int jp = 0; jp < 2; jp++) {
                float lo, hi;
                unpack2(accp[i][jp], lo, hi);
                Hcs[bgrp * 4 + i][hgrp * 4 + jp * 2]     = tanhf(lo);
                Hcs[bgrp * 4 + i][hgrp * 4 + jp * 2 + 1] = tanhf(hi);
            }
        }

        for (int idx = tid; idx < 640; idx += 256) {
            int hi = idx / 10, c = idx % 10;
            int h = hc + hi;
            Wbs[hi][c] = (h < 600) ? Wbn[(size_t)h * 10 + c] : 0.f;
        }
        __syncthreads();

        if (tid < 128) {
            int bq = tid >> 1, c0 = (tid & 1) * 5;
            #pragma unroll
            for (int c = 0; c < 5; c++) {
                float s = 0.f;
                #pragma unroll 8
                for (int hj = 0; hj < 64; hj++)
                    s = fmaf(Hcs[bq][hj], Wbs[hj][c0 + c], s);
                lg[bq][c0 + c] += s;
            }
        }
    }
    __syncthreads();

    if (tid < 64) {
        float l[10];
        #pragma unroll
        for (int c = 0; c < 10; c++) l[c] = lg[tid][c];
        float m = l[0];
        #pragma unroll
        for (int c = 1; c < 10; c++) m = fmaxf(m, l[c]);
        float e[10]; float s = 0.f;
        #pragma unroll
        for (int c = 0; c < 10; c++) { e[c] = expf(l[c] - m); s += e[c]; }
        float inv = 1.f / s;
        size_t base = ((size_t)n * B + b0 + tid) * 10;
        #pragma unroll
        for (int c = 0; c < 10; c++) outp[base + c] = e[c] * inv;
    }
}

// ---------------------------------------------------------------------------
__global__ void mean_kernel(const float* __restrict__ second, float* __restrict__ outm, int B)
{
    int idx = blockIdx.x * blockDim.x + threadIdx.x;
    if (idx >= B * 10) return;
    float s = 0.f;
    #pragma unroll
    for (int n = 0; n < 25; n++) s += second[(size_t)n * B * 10 + idx];
    outm[idx] = s * (1.f / 25.f);
}

// ---------------------------------------------------------------------------
extern "C" void kernel_launch(void* const* d_in, const int* in_sizes, int n_in,
                              void* d_out, int out_size)
{
    const float* x  = (const float*)d_in[0];
    const float* W1 = (const float*)d_in[1];
    const float* b1 = (const float*)d_in[2];
    const float* g1 = (const float*)d_in[3];
    const float* be1= (const float*)d_in[4];
    const float* m1 = (const float*)d_in[5];
    const float* v1 = (const float*)d_in[6];
    const float* W2 = (const float*)d_in[7];
    const float* b2 = (const float*)d_in[8];
    const float* g2 = (const float*)d_in[9];
    const float* be2= (const float*)d_in[10];
    const float* m2 = (const float*)d_in[11];
    const float* v2 = (const float*)d_in[12];
    const float* W3 = (const float*)d_in[13];
    const float* b3 = (const float*)d_in[14];
    const float* g3 = (const float*)d_in[15];
    const float* be3= (const float*)d_in[16];
    const float* m3 = (const float*)d_in[17];
    const float* v3 = (const float*)d_in[18];
    const float* W4 = (const float*)d_in[19];
    const float* b4 = (const float*)d_in[20];
    const float* g4 = (const float*)d_in[21];
    const float* be4= (const float*)d_in[22];
    const float* m4 = (const float*)d_in[23];
    const float* v4 = (const float*)d_in[24];
    const float* Wa = (const float*)d_in[25];
    const float* ba = (const float*)d_in[26];
    const float* Wb = (const float*)d_in[27];
    const float* bb = (const float*)d_in[28];

    const int B = in_sizes[0] / (3 * 20 * 20);

    float *conv1b, *pool1b, *conv2b, *pool2b, *conv3b, *featb, *predsb, *scaleb, *biasb;
    cudaGetSymbolAddress((void**)&conv1b, g_conv1);
    cudaGetSymbolAddress((void**)&pool1b, g_pool1);
    cudaGetSymbolAddress((void**)&conv2b, g_conv2);
    cudaGetSymbolAddress((void**)&pool2b, g_pool2);
    cudaGetSymbolAddress((void**)&conv3b, g_conv3);
    cudaGetSymbolAddress((void**)&featb,  g_feat);
    cudaGetSymbolAddress((void**)&predsb, g_preds);
    cudaGetSymbolAddress((void**)&scaleb, g_scale);
    cudaGetSymbolAddress((void**)&biasb,  g_bias);

    const int smem1 = (3 * 49 + 64 * 27) * 4;
    const int smem2 = (8 * 49 + 128 * 73) * 4;
    const int smem3 = (8 * 49 + 256 * 73) * 4;
    cudaFuncSetAttribute(conv_bn_relu_kernel<3, 64, 3, 20, 64, false>,
                         cudaFuncAttributeMaxDynamicSharedMemorySize, smem1);
    cudaFuncSetAttribute(conv_bn_relu_kernel<64, 128, 8, 10, 128, false>,
                         cudaFuncAttributeMaxDynamicSharedMemorySize, smem2);
    cudaFuncSetAttribute(conv_bn_relu_kernel<128, 256, 8, 5, 256, false>,
                         cudaFuncAttributeMaxDynamicSharedMemorySize, smem3);
    cudaFuncSetAttribute(conv_bn_relu_kernel<256, 256, 8, 5, 256, true>,
                         cudaFuncAttributeMaxDynamicSharedMemorySize, smem3);

    bn_prep<<<1, 64>>> (b1, g1, be1, m1, v1, 64, 0);
    bn_prep<<<1, 128>>>(b2, g2, be2, m2, v2, 128, 64);
    bn_prep<<<1, 256>>>(b3, g3, be3, m3, v3, 256, 192);
    bn_prep<<<1, 256>>>(b4, g4, be4, m4, v4, 256, 448);

    conv_bn_relu_kernel<3, 64, 3, 20, 64, false>
        <<<dim3(16, B), 64, smem1>>>(x, W1, scaleb + 0, biasb + 0, conv1b, B);
    {
        size_t total = (size_t)B * 64 * 100;
        maxpool_kernel<<<(unsigned)((total + 255) / 256), 256>>>(conv1b, pool1b, B, 64, 20);
    }
    conv_bn_relu_kernel<64, 128, 8, 10, 128, false>
        <<<dim3(4, B), 128, smem2>>>(pool1b, W2, scaleb + 64, biasb + 64, conv2b, B);
    {
        size_t total = (size_t)B * 128 * 25;
        maxpool_kernel<<<(unsigned)((total + 255) / 256), 256>>>(conv2b, pool2b, B, 128, 10);
    }
    conv_bn_relu_kernel<128, 256, 8, 5, 256, false>
        <<<dim3(1, B), 256, smem3>>>(pool2b, W3, scaleb + 192, biasb + 192, conv3b, B);
    conv_bn_relu_kernel<256, 256, 8, 5, 256, true>
        <<<dim3(1, B), 256, smem3>>>(conv3b, W4, scaleb + 448, biasb + 448, featb, B);

    float* out   = (float*)d_out;
    float* secnd = out + (size_t)B * 10;

    mlp_kernel<256, false><<<dim3(B / 64, 25), 256>>>(featb, predsb, Wa, ba, Wb, bb, predsb, B);
    mlp_kernel<336, true><<<dim3(B / 64, 25), 256>>>(featb, predsb, Wa, ba, Wb, bb, secnd, B);
    mean_kernel<<<(B * 10 + 255) / 256, 256>>>(secnd, out, B);
}